// round 2
// baseline (speedup 1.0000x reference)
#include <cuda_runtime.h>
#include <math.h>

#define N_UD   500000
#define N_USER 4000
#define N_SUP  300
#define H      128
#define HH     (H*H)
#define E_BIG  500000
#define E_SMALL 4000
#define SZ_U   (N_USER*H)
#define SZ_S   (N_SUP*H)

// ---------------- scratch (static __device__ -> no allocations) ----------------
__device__ __align__(16) float g_hud0[(size_t)N_UD*H];   // feat+emb
__device__ __align__(16) float g_hud1[(size_t)N_UD*H];   // layer1 out (pre-relu)
__device__ __align__(16) float g_user0[SZ_U];
__device__ __align__(16) float g_user1[SZ_U];
__device__ __align__(16) float g_sup0[SZ_S];
__device__ __align__(16) float g_sup1[SZ_S];
__device__ __align__(16) float g_tuser[SZ_U];            // transformed user rows for scatter

#define AGG_TOT (2*(2*SZ_U+SZ_S))
__device__ __align__(16) float g_agg[AGG_TOT];
#define L1_UB 0
#define L1_US (SZ_U)
#define L1_S  (2*SZ_U)
#define L2_UB (2*SZ_U+SZ_S)
#define L2_US (L2_UB+SZ_U)
#define L2_S  (L2_UB+2*SZ_U)

// ---------------- helpers ----------------
__device__ __forceinline__ unsigned long long ffma2(unsigned long long a,
                                                    unsigned long long b,
                                                    unsigned long long c) {
    unsigned long long d;
    asm("fma.rn.f32x2 %0, %1, %2, %3;" : "=l"(d) : "l"(a), "l"(b), "l"(c));
    return d;
}

__device__ __forceinline__ void red_add_v4(float* p, float4 v) {
    asm volatile("red.global.add.v4.f32 [%0], {%1,%2,%3,%4};"
                 :: "l"(p), "f"(v.x), "f"(v.y), "f"(v.z), "f"(v.w) : "memory");
}

// ---------------- zero agg buffers ----------------
__global__ void k_zero_agg() {
    int g = blockIdx.x * blockDim.x + threadIdx.x;
    float4* p = (float4*)g_agg;
    if (g < AGG_TOT/4) p[g] = make_float4(0.f,0.f,0.f,0.f);
}

// ---------------- gather embedding rows via nid ----------------
__global__ void k_gather_rows(const float* __restrict__ emb, const int* __restrict__ nid,
                              float* __restrict__ out, int M) {
    int g = blockIdx.x * blockDim.x + threadIdx.x;
    int row = g >> 5, lane = g & 31;
    if (row >= M) return;
    int r = nid[row];
    float4 v = *(const float4*)(emb + (size_t)r*H + lane*4);
    *(float4*)(out + (size_t)row*H + lane*4) = v;
}

// ---------------- h_ud0 = x_ud @ W_feat + b_feat + emb_ud[nid] ----------------
__global__ void k_feat(const float* __restrict__ xud, const float* __restrict__ Wf,
                       const float* __restrict__ bf, const float* __restrict__ emb,
                       const int* __restrict__ nid, float* __restrict__ out) {
    int g = blockIdx.x * blockDim.x + threadIdx.x;
    int row = g >> 5, lane = g & 31;
    if (row >= N_UD) return;
    float x0 = xud[row*5+0], x1 = xud[row*5+1], x2 = xud[row*5+2],
          x3 = xud[row*5+3], x4 = xud[row*5+4];
    int r = nid[row];
    int c = lane * 4;
    float4 e = *(const float4*)(emb + (size_t)r*H + c);
    float4 b = *(const float4*)(bf + c);
    float4 w0 = *(const float4*)(Wf + 0*H + c);
    float4 w1 = *(const float4*)(Wf + 1*H + c);
    float4 w2 = *(const float4*)(Wf + 2*H + c);
    float4 w3 = *(const float4*)(Wf + 3*H + c);
    float4 w4 = *(const float4*)(Wf + 4*H + c);
    float4 o;
    o.x = b.x + e.x + x0*w0.x + x1*w1.x + x2*w2.x + x3*w3.x + x4*w4.x;
    o.y = b.y + e.y + x0*w0.y + x1*w1.y + x2*w2.y + x3*w3.y + x4*w4.y;
    o.z = b.z + e.z + x0*w0.z + x1*w1.z + x2*w2.z + x3*w3.z + x4*w4.z;
    o.w = b.w + e.w + x0*w0.w + x1*w1.w + x2*w2.w + x3*w3.w + x4*w4.w;
    *(float4*)(out + (size_t)row*H + c) = o;
}

// ---------------- edge scatter-add: dst[ed[e]] += (relu?)src[es[e]] ----------------
template<bool RELU>
__global__ void k_edge_add(const float* __restrict__ src_tab, const int* __restrict__ es,
                           const int* __restrict__ ed, float* __restrict__ dst_tab, int E) {
    int g = blockIdx.x * blockDim.x + threadIdx.x;
    int e = g >> 5;
    if (e >= E) return;
    int lane = g & 31;
    int s = es[e], d = ed[e];
    float4 v = *(const float4*)(src_tab + (size_t)s*H + lane*4);
    if (RELU) { v.x=fmaxf(v.x,0.f); v.y=fmaxf(v.y,0.f); v.z=fmaxf(v.z,0.f); v.w=fmaxf(v.w,0.f); }
    red_add_v4(dst_tab + (size_t)d*H + lane*4, v);
}

// ---------------- small GEMM: C (=|+=) A@W (+bias) (relu) ----------------
__global__ void k_gemm_small(const float* __restrict__ A, const float* __restrict__ W,
                             const float* __restrict__ bias, float* __restrict__ C,
                             int M, int accum, int relu) {
    int g = blockIdx.x * blockDim.x + threadIdx.x;
    int row = g >> 5;
    if (row >= M) return;
    int lane = g & 31;
    const float* a = A + (size_t)row*H;
    float4 acc = make_float4(0.f,0.f,0.f,0.f);
    #pragma unroll 8
    for (int k = 0; k < H; ++k) {
        float av = __ldg(a + k);
        float4 w = *(const float4*)(W + (size_t)k*H + lane*4);
        acc.x += av*w.x; acc.y += av*w.y; acc.z += av*w.z; acc.w += av*w.w;
    }
    if (bias) {
        float4 b = *(const float4*)(bias + lane*4);
        acc.x += b.x; acc.y += b.y; acc.z += b.z; acc.w += b.w;
    }
    float* cp = C + (size_t)row*H + lane*4;
    if (accum) {
        float4 old = *(float4*)cp;
        acc.x += old.x; acc.y += old.y; acc.z += old.z; acc.w += old.w;
    }
    if (relu) { acc.x=fmaxf(acc.x,0.f); acc.y=fmaxf(acc.y,0.f); acc.z=fmaxf(acc.z,0.f); acc.w=fmaxf(acc.w,0.f); }
    *(float4*)cp = acc;
}

// ---------------- big GEMM: C[M,128] = (relu?)A[M,128] @ W[128,128] + bias ----------------
#define GB_THREADS 256
#define GB_TILE 128
#define GB_KC 32
#define SA_STRIDE 130   // float2 units per k-row (16B-aligned rows, conflict-spread)
#define GB_SMEM_BYTES (HH*4 + GB_KC*SA_STRIDE*8)

template<bool RELU>
__global__ __launch_bounds__(GB_THREADS, 2)
void k_gemm_big(const float* __restrict__ A, const float* __restrict__ W,
                const float* __restrict__ bias, float* __restrict__ C, int M) {
    extern __shared__ char smem[];
    float*  sW = (float*)smem;
    float2* sA = (float2*)(smem + HH*4);

    int tid = threadIdx.x;
    int tx = tid & 15, ty = tid >> 4;
    long blockRow = (long)blockIdx.x * GB_TILE;

    // W -> smem (16384 floats)
    {
        const float4* Wv = (const float4*)W;
        float4* sWv = (float4*)sW;
        #pragma unroll
        for (int i = 0; i < 16; ++i) sWv[tid + i*GB_THREADS] = Wv[tid + i*GB_THREADS];
    }

    unsigned long long acc[8][4];
    #pragma unroll
    for (int r = 0; r < 8; ++r)
        #pragma unroll
        for (int q = 0; q < 4; ++q) acc[r][q] = 0ull;

    int lr = tid >> 3;          // 0..31 (row within group of 32)
    int lk = (tid & 7) << 2;    // 0,4,...,28 (k offset within chunk)

    float4 v[4];
    #pragma unroll
    for (int i = 0; i < 4; ++i) {
        long row = blockRow + lr + 32*i; if (row >= M) row = M-1;
        float4 t = *(const float4*)(A + row*H + lk);
        if (RELU) { t.x=fmaxf(t.x,0.f); t.y=fmaxf(t.y,0.f); t.z=fmaxf(t.z,0.f); t.w=fmaxf(t.w,0.f); }
        v[i] = t;
    }

    for (int ch = 0; ch < H/GB_KC; ++ch) {
        __syncthreads();
        #pragma unroll
        for (int i = 0; i < 4; ++i) {
            int r = lr + 32*i;
            sA[(lk+0)*SA_STRIDE + r] = make_float2(v[i].x, v[i].x);
            sA[(lk+1)*SA_STRIDE + r] = make_float2(v[i].y, v[i].y);
            sA[(lk+2)*SA_STRIDE + r] = make_float2(v[i].z, v[i].z);
            sA[(lk+3)*SA_STRIDE + r] = make_float2(v[i].w, v[i].w);
        }
        __syncthreads();
        if (ch + 1 < H/GB_KC) {
            int kc = (ch+1) * GB_KC;
            #pragma unroll
            for (int i = 0; i < 4; ++i) {
                long row = blockRow + lr + 32*i; if (row >= M) row = M-1;
                float4 t = *(const float4*)(A + row*H + kc + lk);
                if (RELU) { t.x=fmaxf(t.x,0.f); t.y=fmaxf(t.y,0.f); t.z=fmaxf(t.z,0.f); t.w=fmaxf(t.w,0.f); }
                v[i] = t;
            }
        }
        int kbase = ch * GB_KC;
        #pragma unroll
        for (int k = 0; k < GB_KC; ++k) {
            const float2* ap = sA + k*SA_STRIDE;
            ulonglong2 a01 = *(const ulonglong2*)(ap + 4*ty);
            ulonglong2 a23 = *(const ulonglong2*)(ap + 4*ty + 2);
            ulonglong2 a45 = *(const ulonglong2*)(ap + 64 + 4*ty);
            ulonglong2 a67 = *(const ulonglong2*)(ap + 66 + 4*ty);
            const float* wrow = sW + (kbase + k)*H;
            ulonglong2 w01 = *(const ulonglong2*)(wrow + 4*tx);
            ulonglong2 w23 = *(const ulonglong2*)(wrow + 64 + 4*tx);
            unsigned long long a[8] = {a01.x, a01.y, a23.x, a23.y, a45.x, a45.y, a67.x, a67.y};
            unsigned long long w[4] = {w01.x, w01.y, w23.x, w23.y};
            #pragma unroll
            for (int r = 0; r < 8; ++r) {
                #pragma unroll
                for (int q = 0; q < 4; ++q) acc[r][q] = ffma2(a[r], w[q], acc[r][q]);
            }
        }
    }

    float2 b0 = *(const float2*)(bias + 4*tx);
    float2 b1 = *(const float2*)(bias + 4*tx + 2);
    float2 b2 = *(const float2*)(bias + 64 + 4*tx);
    float2 b3 = *(const float2*)(bias + 66 + 4*tx);
    #pragma unroll
    for (int r = 0; r < 8; ++r) {
        long row = blockRow + ((r < 4) ? (4*ty + r) : (64 + 4*ty + (r-4)));
        if (row < M) {
            float2 f0 = *(float2*)&acc[r][0];
            float2 f1 = *(float2*)&acc[r][1];
            float2 f2 = *(float2*)&acc[r][2];
            float2 f3 = *(float2*)&acc[r][3];
            *(float4*)(C + row*H + 4*tx)      = make_float4(f0.x+b0.x, f0.y+b0.y, f1.x+b1.x, f1.y+b1.y);
            *(float4*)(C + row*H + 64 + 4*tx) = make_float4(f2.x+b2.x, f2.y+b2.y, f3.x+b3.x, f3.y+b3.y);
        }
    }
}

// ---------------- pred = log_softmax(h_ud @ W_out + b_out) ----------------
__global__ void k_pred(const float* __restrict__ hud, const float* __restrict__ Wout,
                       const float* __restrict__ bout, float* __restrict__ pred) {
    int g = blockIdx.x * blockDim.x + threadIdx.x;
    int row = g >> 5;
    if (row >= N_UD) return;
    int lane = g & 31;
    float4 h = *(const float4*)(hud + (size_t)row*H + lane*4);
    const float4* wp = (const float4*)(Wout + lane*8);   // k = 4*lane .. 4*lane+3, 2 outs each
    float4 wa = wp[0], wb = wp[1];
    float z0 = h.x*wa.x + h.y*wa.z + h.z*wb.x + h.w*wb.z;
    float z1 = h.x*wa.y + h.y*wa.w + h.z*wb.y + h.w*wb.w;
    #pragma unroll
    for (int o = 16; o > 0; o >>= 1) {
        z0 += __shfl_down_sync(0xffffffffu, z0, o);
        z1 += __shfl_down_sync(0xffffffffu, z1, o);
    }
    if (lane == 0) {
        z0 += bout[0]; z1 += bout[1];
        float m = fmaxf(z0, z1);
        float l = m + logf(expf(z0 - m) + expf(z1 - m));
        *(float2*)(pred + (size_t)row*2) = make_float2(z0 - l, z1 - l);
    }
}

// ---------------- launch ----------------
extern "C" void kernel_launch(void* const* d_in, const int* in_sizes, int n_in,
                              void* d_out, int out_size) {
    const float* x_ud   = (const float*)d_in[0];
    const float* W_feat = (const float*)d_in[1];
    const float* b_feat = (const float*)d_in[2];
    const float* emb_ud = (const float*)d_in[3];
    const float* emb_us = (const float*)d_in[4];
    const float* emb_sp = (const float*)d_in[5];
    const float* Wr1 = (const float*)d_in[6];
    const float* br1 = (const float*)d_in[7];
    const float* Wt1 = (const float*)d_in[8];
    const float* Wr2 = (const float*)d_in[9];
    const float* br2 = (const float*)d_in[10];
    const float* Wt2 = (const float*)d_in[11];
    const float* Wout = (const float*)d_in[12];
    const float* bout = (const float*)d_in[13];
    const int* nid_ud = (const int*)d_in[14];
    const int* nid_us = (const int*)d_in[15];
    const int* nid_sp = (const int*)d_in[16];
    const int* e0s = (const int*)d_in[17];
    const int* e0d = (const int*)d_in[18];
    const int* e1s = (const int*)d_in[19];
    const int* e1d = (const int*)d_in[20];
    const int* e2s = (const int*)d_in[21];
    const int* e2d = (const int*)d_in[22];
    const int* e3s = (const int*)d_in[23];
    const int* e3d = (const int*)d_in[24];

    float *p_hud0, *p_hud1, *p_user0, *p_user1, *p_sup0, *p_sup1, *p_tuser, *p_agg;
    cudaGetSymbolAddress((void**)&p_hud0,  g_hud0);
    cudaGetSymbolAddress((void**)&p_hud1,  g_hud1);
    cudaGetSymbolAddress((void**)&p_user0, g_user0);
    cudaGetSymbolAddress((void**)&p_user1, g_user1);
    cudaGetSymbolAddress((void**)&p_sup0,  g_sup0);
    cudaGetSymbolAddress((void**)&p_sup1,  g_sup1);
    cudaGetSymbolAddress((void**)&p_tuser, g_tuser);
    cudaGetSymbolAddress((void**)&p_agg,   g_agg);

    float* out    = (float*)d_out;
    float* o_pred = out;
    float* o_hud  = out + 1000000;
    float* o_user = out + 65000000;
    float* o_sup  = out + 65512000;

    cudaFuncSetAttribute(k_gemm_big<false>, cudaFuncAttributeMaxDynamicSharedMemorySize, GB_SMEM_BYTES);
    cudaFuncSetAttribute(k_gemm_big<true>,  cudaFuncAttributeMaxDynamicSharedMemorySize, GB_SMEM_BYTES);

    const int T = 256;
    int gridZero  = (AGG_TOT/4 + T-1)/T;
    int gridUD32  = (N_UD*32 + T-1)/T;
    int gridUs32  = (N_USER*32 + T-1)/T;
    int gridSp32  = (N_SUP*32 + T-1)/T;
    int gridEB    = (E_BIG*32 + T-1)/T;
    int gridES    = (E_SMALL*32 + T-1)/T;
    int gridBig   = (N_UD + GB_TILE-1)/GB_TILE;

    k_zero_agg<<<gridZero, T>>>();
    k_gather_rows<<<gridUs32, T>>>(emb_us, nid_us, p_user0, N_USER);
    k_gather_rows<<<gridSp32, T>>>(emb_sp, nid_sp, p_sup0, N_SUP);
    k_feat<<<gridUD32, T>>>(x_ud, W_feat, b_feat, emb_ud, nid_ud, p_hud0);

    // ---- layer 1 aggregations into small tables ----
    k_edge_add<false><<<gridEB, T>>>(p_hud0,  e0s, e0d, p_agg + L1_UB, E_BIG);
    k_edge_add<false><<<gridES, T>>>(p_sup0,  e3s, e3d, p_agg + L1_US, E_SMALL);
    k_edge_add<false><<<gridES, T>>>(p_user0, e2s, e2d, p_agg + L1_S,  E_SMALL);

    // ---- layer 1 user/sup outputs ----
    k_gemm_small<<<gridUs32, T>>>(p_agg + L1_UB, Wr1 + 0*HH, br1 + 0*H, p_user1, N_USER, 0, 0);
    k_gemm_small<<<gridUs32, T>>>(p_agg + L1_US, Wr1 + 3*HH, br1 + 3*H, p_user1, N_USER, 1, 0);
    k_gemm_small<<<gridUs32, T>>>(p_user0,       Wt1 + 0*HH, nullptr,   p_user1, N_USER, 1, 0);
    k_gemm_small<<<gridUs32, T>>>(p_user0,       Wt1 + 3*HH, nullptr,   p_user1, N_USER, 1, 1);
    k_gemm_small<<<gridSp32, T>>>(p_agg + L1_S,  Wr1 + 2*HH, br1 + 2*H, p_sup1,  N_SUP,  0, 0);
    k_gemm_small<<<gridSp32, T>>>(p_sup0,        Wt1 + 2*HH, nullptr,   p_sup1,  N_SUP,  1, 1);

    // ---- layer 1 UD: h_ud1 = h_ud0 @ Wroot + b + scatter(user0 @ Wrel) ----
    k_gemm_small<<<gridUs32, T>>>(p_user0, Wr1 + 1*HH, nullptr, p_tuser, N_USER, 0, 0);
    k_gemm_big<false><<<gridBig, GB_THREADS, GB_SMEM_BYTES>>>(p_hud0, Wt1 + 1*HH, br1 + 1*H, p_hud1, N_UD);
    k_edge_add<false><<<gridEB, T>>>(p_tuser, e1s, e1d, p_hud1, E_BIG);

    // ---- layer 2 aggregations (relu applied when reading h_ud1) ----
    k_edge_add<true ><<<gridEB, T>>>(p_hud1,  e0s, e0d, p_agg + L2_UB, E_BIG);
    k_edge_add<false><<<gridES, T>>>(p_sup1,  e3s, e3d, p_agg + L2_US, E_SMALL);
    k_edge_add<false><<<gridES, T>>>(p_user1, e2s, e2d, p_agg + L2_S,  E_SMALL);

    // ---- layer 2 user/sup outputs (straight into d_out) ----
    k_gemm_small<<<gridUs32, T>>>(p_agg + L2_UB, Wr2 + 0*HH, br2 + 0*H, o_user, N_USER, 0, 0);
    k_gemm_small<<<gridUs32, T>>>(p_agg + L2_US, Wr2 + 3*HH, br2 + 3*H, o_user, N_USER, 1, 0);
    k_gemm_small<<<gridUs32, T>>>(p_user1,       Wt2 + 0*HH, nullptr,   o_user, N_USER, 1, 0);
    k_gemm_small<<<gridUs32, T>>>(p_user1,       Wt2 + 3*HH, nullptr,   o_user, N_USER, 1, 0);
    k_gemm_small<<<gridSp32, T>>>(p_agg + L2_S,  Wr2 + 2*HH, br2 + 2*H, o_sup,  N_SUP,  0, 0);
    k_gemm_small<<<gridSp32, T>>>(p_sup1,        Wt2 + 2*HH, nullptr,   o_sup,  N_SUP,  1, 0);

    // ---- layer 2 UD (straight into d_out) ----
    k_gemm_small<<<gridUs32, T>>>(p_user1, Wr2 + 1*HH, nullptr, p_tuser, N_USER, 0, 0);
    k_gemm_big<true><<<gridBig, GB_THREADS, GB_SMEM_BYTES>>>(p_hud1, Wt2 + 1*HH, br2 + 1*H, o_hud, N_UD);
    k_edge_add<false><<<gridEB, T>>>(p_tuser, e1s, e1d, o_hud, E_BIG);

    // ---- prediction head ----
    k_pred<<<gridUD32, T>>>(o_hud, Wout, bout, o_pred);

    (void)in_sizes; (void)n_in; (void)out_size;
}

// round 3
// speedup vs baseline: 1.0781x; 1.0781x over previous
#include <cuda_runtime.h>
#include <math.h>

#define N_UD   500000
#define N_USER 4000
#define N_SUP  300
#define H      128
#define HH     (H*H)
#define E_BIG  500000
#define E_SMALL 4000
#define SZ_U   (N_USER*H)
#define SZ_S   (N_SUP*H)
#define NBLK   489   // ceil(N_UD/1024)

// ---------------- scratch (static __device__ -> no allocations) ----------------
__device__ __align__(16) float g_hud0[(size_t)N_UD*H];
__device__ __align__(16) float g_hud1[(size_t)N_UD*H];
__device__ __align__(16) float g_user0[SZ_U];
__device__ __align__(16) float g_user1[SZ_U];
__device__ __align__(16) float g_sup0[SZ_S];
__device__ __align__(16) float g_sup1[SZ_S];
__device__ __align__(16) float g_tuser[SZ_U];

// CSR scratch for edge type 1 (user -> UD), keyed by dst (UD node)
__device__ int g_cnt[N_UD];
__device__ int g_rowptr[N_UD];
__device__ int g_pos[N_UD];
__device__ int g_csrc[E_BIG];
__device__ int g_bsum[NBLK];
__device__ int g_boff[NBLK];

#define AGG_TOT (2*(2*SZ_U+SZ_S))
__device__ __align__(16) float g_agg[AGG_TOT];
#define L1_UB 0
#define L1_US (SZ_U)
#define L1_S  (2*SZ_U)
#define L2_UB (2*SZ_U+SZ_S)
#define L2_US (L2_UB+SZ_U)
#define L2_S  (L2_UB+2*SZ_U)

// ---------------- helpers ----------------
__device__ __forceinline__ unsigned long long ffma2(unsigned long long a,
                                                    unsigned long long b,
                                                    unsigned long long c) {
    unsigned long long d;
    asm("fma.rn.f32x2 %0, %1, %2, %3;" : "=l"(d) : "l"(a), "l"(b), "l"(c));
    return d;
}

__device__ __forceinline__ void red_add_v4(float* p, float4 v) {
    asm volatile("red.global.add.v4.f32 [%0], {%1,%2,%3,%4};"
                 :: "l"(p), "f"(v.x), "f"(v.y), "f"(v.z), "f"(v.w) : "memory");
}

// ---------------- zero kernels ----------------
__global__ void k_zero_agg() {
    int g = blockIdx.x * blockDim.x + threadIdx.x;
    float4* p = (float4*)g_agg;
    if (g < AGG_TOT/4) p[g] = make_float4(0.f,0.f,0.f,0.f);
}
__global__ void k_zero_cnt() {
    int g = blockIdx.x * blockDim.x + threadIdx.x;
    if (g < N_UD) g_cnt[g] = 0;
}

// ---------------- CSR build (dst-keyed) ----------------
__global__ void k_hist(const int* __restrict__ ed) {
    int e = blockIdx.x * blockDim.x + threadIdx.x;
    if (e < E_BIG) atomicAdd(&g_cnt[ed[e]], 1);
}
__global__ void k_bsum() {
    __shared__ int s[256];
    int b = blockIdx.x, t = threadIdx.x;
    int sum = 0;
    for (int i = t; i < 1024; i += 256) {
        int idx = b*1024 + i;
        if (idx < N_UD) sum += g_cnt[idx];
    }
    s[t] = sum; __syncthreads();
    for (int o = 128; o > 0; o >>= 1) { if (t < o) s[t] += s[t+o]; __syncthreads(); }
    if (t == 0) g_bsum[b] = s[0];
}
__global__ void k_scan_top() {
    __shared__ int s[512];
    int t = threadIdx.x;
    int v = (t < NBLK) ? g_bsum[t] : 0;
    s[t] = v; __syncthreads();
    for (int o = 1; o < 512; o <<= 1) {
        int x = (t >= o) ? s[t-o] : 0;
        __syncthreads(); s[t] += x; __syncthreads();
    }
    if (t < NBLK) g_boff[t] = s[t] - v;
}
__global__ void k_scan_write() {
    __shared__ int s[1024];
    int b = blockIdx.x, t = threadIdx.x;
    int idx = b*1024 + t;
    int v = (idx < N_UD) ? g_cnt[idx] : 0;
    s[t] = v; __syncthreads();
    for (int o = 1; o < 1024; o <<= 1) {
        int x = (t >= o) ? s[t-o] : 0;
        __syncthreads(); s[t] += x; __syncthreads();
    }
    if (idx < N_UD) {
        int r = g_boff[b] + s[t] - v;
        g_rowptr[idx] = r;
        g_pos[idx] = r;
    }
}
__global__ void k_fill(const int* __restrict__ es, const int* __restrict__ ed) {
    int e = blockIdx.x * blockDim.x + threadIdx.x;
    if (e >= E_BIG) return;
    int p = atomicAdd(&g_pos[ed[e]], 1);
    g_csrc[p] = es[e];
}

// ---------------- gather embedding rows via nid ----------------
__global__ void k_gather_rows(const float* __restrict__ emb, const int* __restrict__ nid,
                              float* __restrict__ out, int M) {
    int g = blockIdx.x * blockDim.x + threadIdx.x;
    int row = g >> 5, lane = g & 31;
    if (row >= M) return;
    int r = nid[row];
    float4 v = *(const float4*)(emb + (size_t)r*H + lane*4);
    *(float4*)(out + (size_t)row*H + lane*4) = v;
}

// ---------------- edge scatter-add (small dst tables, L2-resident) ----------------
template<bool RELU>
__global__ void k_edge_add(const float* __restrict__ src_tab, const int* __restrict__ es,
                           const int* __restrict__ ed, float* __restrict__ dst_tab, int E) {
    int g = blockIdx.x * blockDim.x + threadIdx.x;
    int e = g >> 5;
    if (e >= E) return;
    int lane = g & 31;
    int s = es[e], d = ed[e];
    float4 v = *(const float4*)(src_tab + (size_t)s*H + lane*4);
    if (RELU) { v.x=fmaxf(v.x,0.f); v.y=fmaxf(v.y,0.f); v.z=fmaxf(v.z,0.f); v.w=fmaxf(v.w,0.f); }
    red_add_v4(dst_tab + (size_t)d*H + lane*4, v);
}

// ---------------- small GEMM ----------------
__global__ void k_gemm_small(const float* __restrict__ A, const float* __restrict__ W,
                             const float* __restrict__ bias, float* __restrict__ C,
                             int M, int accum, int relu) {
    int g = blockIdx.x * blockDim.x + threadIdx.x;
    int row = g >> 5;
    if (row >= M) return;
    int lane = g & 31;
    const float* a = A + (size_t)row*H;
    float4 acc = make_float4(0.f,0.f,0.f,0.f);
    #pragma unroll 8
    for (int k = 0; k < H; ++k) {
        float av = __ldg(a + k);
        float4 w = *(const float4*)(W + (size_t)k*H + lane*4);
        acc.x += av*w.x; acc.y += av*w.y; acc.z += av*w.z; acc.w += av*w.w;
    }
    if (bias) {
        float4 b = *(const float4*)(bias + lane*4);
        acc.x += b.x; acc.y += b.y; acc.z += b.z; acc.w += b.w;
    }
    float* cp = C + (size_t)row*H + lane*4;
    if (accum) {
        float4 old = *(float4*)cp;
        acc.x += old.x; acc.y += old.y; acc.z += old.z; acc.w += old.w;
    }
    if (relu) { acc.x=fmaxf(acc.x,0.f); acc.y=fmaxf(acc.y,0.f); acc.z=fmaxf(acc.z,0.f); acc.w=fmaxf(acc.w,0.f); }
    *(float4*)cp = acc;
}

// ---------------- fused big GEMM ----------------
// MODE 1: A = feat(x_ud, Wf, bf, emb[nid]) computed inline (side-writes hud0);
//         C = A@W + bias + CSR-scatter(tuser)
// MODE 2: A = relu(hud1); C = A@W + bias + CSR-scatter(tuser); also writes
//         pred = log_softmax(C @ Wout + bout)
#define GB_THREADS 256
#define GB_TILE 128
#define GB_KC 32
#define SA_STRIDE 130
#define GB_EXTRA 4096
#define GB_SMEM_BYTES (HH*4 + GB_KC*SA_STRIDE*8 + GB_EXTRA)

template<int MODE>
__device__ __forceinline__ float4 loadA(const float* __restrict__ A,
                                        const float* __restrict__ xud,
                                        const int* __restrict__ nid,
                                        const float* __restrict__ emb,
                                        const float* __restrict__ sEx,
                                        float* __restrict__ hud0,
                                        long row, int kk) {
    if (MODE == 1) {
        int r = nid[row];
        const float* x = xud + row*5;
        float x0=x[0], x1=x[1], x2=x[2], x3=x[3], x4=x[4];
        float4 e  = *(const float4*)(emb + (size_t)r*H + kk);
        float4 w0 = *(const float4*)(sEx + 0*H + kk);
        float4 w1 = *(const float4*)(sEx + 1*H + kk);
        float4 w2 = *(const float4*)(sEx + 2*H + kk);
        float4 w3 = *(const float4*)(sEx + 3*H + kk);
        float4 w4 = *(const float4*)(sEx + 4*H + kk);
        float4 bb = *(const float4*)(sEx + 5*H + kk);
        float4 o;
        o.x = bb.x + e.x + x0*w0.x + x1*w1.x + x2*w2.x + x3*w3.x + x4*w4.x;
        o.y = bb.y + e.y + x0*w0.y + x1*w1.y + x2*w2.y + x3*w3.y + x4*w4.y;
        o.z = bb.z + e.z + x0*w0.z + x1*w1.z + x2*w2.z + x3*w3.z + x4*w4.z;
        o.w = bb.w + e.w + x0*w0.w + x1*w1.w + x2*w2.w + x3*w3.w + x4*w4.w;
        *(float4*)(hud0 + row*H + kk) = o;
        return o;
    } else {
        float4 t = *(const float4*)(A + row*H + kk);
        t.x=fmaxf(t.x,0.f); t.y=fmaxf(t.y,0.f); t.z=fmaxf(t.z,0.f); t.w=fmaxf(t.w,0.f);
        return t;
    }
}

template<int MODE>
__global__ __launch_bounds__(GB_THREADS, 2)
void k_fused(const float* __restrict__ A, const float* __restrict__ W,
             const float* __restrict__ bias, const float* __restrict__ tuser,
             const int* __restrict__ rowptr, const int* __restrict__ csrc,
             float* __restrict__ C,
             const float* __restrict__ xud, const int* __restrict__ nid,
             const float* __restrict__ emb, const float* __restrict__ Wf,
             const float* __restrict__ bf, float* __restrict__ hud0,
             const float* __restrict__ Wout, const float* __restrict__ bout,
             float* __restrict__ pred, int M) {
    extern __shared__ char smem[];
    float*  sW  = (float*)smem;
    float2* sA  = (float2*)(smem + HH*4);
    float*  sEx = (float*)(smem + HH*4 + GB_KC*SA_STRIDE*8);

    int tid = threadIdx.x;
    int tx = tid & 15, ty = tid >> 4;
    long blockRow = (long)blockIdx.x * GB_TILE;

    // W -> smem (16384 floats)
    {
        const float4* Wv = (const float4*)W;
        float4* sWv = (float4*)sW;
        #pragma unroll
        for (int i = 0; i < 16; ++i) sWv[tid + i*GB_THREADS] = Wv[tid + i*GB_THREADS];
    }
    // extras -> smem
    if (MODE == 1) {
        for (int i = tid; i < 5*H; i += GB_THREADS) sEx[i] = Wf[i];
        if (tid < H) sEx[5*H + tid] = bf[tid];
    } else {
        if (tid < 2*H) sEx[tid] = Wout[tid];
    }
    __syncthreads();

    unsigned long long acc[8][4];
    #pragma unroll
    for (int r = 0; r < 8; ++r)
        #pragma unroll
        for (int q = 0; q < 4; ++q) acc[r][q] = 0ull;

    int lr = tid >> 3;
    int lk = (tid & 7) << 2;

    float4 v[4];
    #pragma unroll
    for (int i = 0; i < 4; ++i) {
        long row = blockRow + lr + 32*i; if (row >= M) row = M-1;
        v[i] = loadA<MODE>(A, xud, nid, emb, sEx, hud0, row, lk);
    }

    for (int ch = 0; ch < H/GB_KC; ++ch) {
        __syncthreads();
        #pragma unroll
        for (int i = 0; i < 4; ++i) {
            int r = lr + 32*i;
            sA[(lk+0)*SA_STRIDE + r] = make_float2(v[i].x, v[i].x);
            sA[(lk+1)*SA_STRIDE + r] = make_float2(v[i].y, v[i].y);
            sA[(lk+2)*SA_STRIDE + r] = make_float2(v[i].z, v[i].z);
            sA[(lk+3)*SA_STRIDE + r] = make_float2(v[i].w, v[i].w);
        }
        __syncthreads();
        if (ch + 1 < H/GB_KC) {
            int kc = (ch+1) * GB_KC;
            #pragma unroll
            for (int i = 0; i < 4; ++i) {
                long row = blockRow + lr + 32*i; if (row >= M) row = M-1;
                v[i] = loadA<MODE>(A, xud, nid, emb, sEx, hud0, row, kc + lk);
            }
        }
        int kbase = ch * GB_KC;
        #pragma unroll
        for (int k = 0; k < GB_KC; ++k) {
            const float2* ap = sA + k*SA_STRIDE;
            ulonglong2 a01 = *(const ulonglong2*)(ap + 4*ty);
            ulonglong2 a23 = *(const ulonglong2*)(ap + 4*ty + 2);
            ulonglong2 a45 = *(const ulonglong2*)(ap + 64 + 4*ty);
            ulonglong2 a67 = *(const ulonglong2*)(ap + 66 + 4*ty);
            const float* wrow = sW + (kbase + k)*H;
            ulonglong2 w01 = *(const ulonglong2*)(wrow + 4*tx);
            ulonglong2 w23 = *(const ulonglong2*)(wrow + 64 + 4*tx);
            unsigned long long a[8] = {a01.x, a01.y, a23.x, a23.y, a45.x, a45.y, a67.x, a67.y};
            unsigned long long w[4] = {w01.x, w01.y, w23.x, w23.y};
            #pragma unroll
            for (int r = 0; r < 8; ++r) {
                #pragma unroll
                for (int q = 0; q < 4; ++q) acc[r][q] = ffma2(a[r], w[q], acc[r][q]);
            }
        }
    }

    // ---------------- epilogue: bias + CSR scatter + store (+ pred) ----------------
    float bb[8];
    {
        float4 b0 = *(const float4*)(bias + 4*tx);
        float4 b1 = *(const float4*)(bias + 64 + 4*tx);
        bb[0]=b0.x; bb[1]=b0.y; bb[2]=b0.z; bb[3]=b0.w;
        bb[4]=b1.x; bb[5]=b1.y; bb[6]=b1.z; bb[7]=b1.w;
    }
    float bo0 = 0.f, bo1 = 0.f;
    if (MODE == 2) { bo0 = bout[0]; bo1 = bout[1]; }

    #pragma unroll
    for (int r = 0; r < 8; ++r) {
        long row = blockRow + ((r < 4) ? (4*ty + r) : (64 + 4*ty + (r-4)));
        long rc = (row < M) ? row : (M-1);
        float cr[8];
        {
            float2 f0 = *(float2*)&acc[r][0];
            float2 f1 = *(float2*)&acc[r][1];
            float2 f2 = *(float2*)&acc[r][2];
            float2 f3 = *(float2*)&acc[r][3];
            cr[0]=f0.x+bb[0]; cr[1]=f0.y+bb[1]; cr[2]=f1.x+bb[2]; cr[3]=f1.y+bb[3];
            cr[4]=f2.x+bb[4]; cr[5]=f2.y+bb[5]; cr[6]=f3.x+bb[6]; cr[7]=f3.y+bb[7];
        }
        // CSR scatter-add of transformed user rows (L2-resident table)
        int beg = rowptr[rc];
        int end = (rc == N_UD-1) ? E_BIG : rowptr[rc+1];
        for (int e = beg; e < end; ++e) {
            int s = csrc[e];
            float4 u0 = *(const float4*)(tuser + (size_t)s*H + 4*tx);
            float4 u1 = *(const float4*)(tuser + (size_t)s*H + 64 + 4*tx);
            cr[0]+=u0.x; cr[1]+=u0.y; cr[2]+=u0.z; cr[3]+=u0.w;
            cr[4]+=u1.x; cr[5]+=u1.y; cr[6]+=u1.z; cr[7]+=u1.w;
        }
        if (row < M) {
            *(float4*)(C + row*H + 4*tx)      = make_float4(cr[0],cr[1],cr[2],cr[3]);
            *(float4*)(C + row*H + 64 + 4*tx) = make_float4(cr[4],cr[5],cr[6],cr[7]);
        }
        if (MODE == 2) {
            float z0 = 0.f, z1 = 0.f;
            #pragma unroll
            for (int j = 0; j < 8; ++j) {
                int col = (j < 4) ? (4*tx + j) : (64 + 4*tx + (j-4));
                z0 += cr[j] * sEx[2*col];
                z1 += cr[j] * sEx[2*col + 1];
            }
            #pragma unroll
            for (int o = 8; o > 0; o >>= 1) {
                z0 += __shfl_xor_sync(0xffffffffu, z0, o);
                z1 += __shfl_xor_sync(0xffffffffu, z1, o);
            }
            if (tx == 0 && row < M) {
                z0 += bo0; z1 += bo1;
                float m = fmaxf(z0, z1);
                float l = m + logf(expf(z0 - m) + expf(z1 - m));
                *(float2*)(pred + row*2) = make_float2(z0 - l, z1 - l);
            }
        }
    }
}

// ---------------- launch ----------------
extern "C" void kernel_launch(void* const* d_in, const int* in_sizes, int n_in,
                              void* d_out, int out_size) {
    const float* x_ud   = (const float*)d_in[0];
    const float* W_feat = (const float*)d_in[1];
    const float* b_feat = (const float*)d_in[2];
    const float* emb_ud = (const float*)d_in[3];
    const float* emb_us = (const float*)d_in[4];
    const float* emb_sp = (const float*)d_in[5];
    const float* Wr1 = (const float*)d_in[6];
    const float* br1 = (const float*)d_in[7];
    const float* Wt1 = (const float*)d_in[8];
    const float* Wr2 = (const float*)d_in[9];
    const float* br2 = (const float*)d_in[10];
    const float* Wt2 = (const float*)d_in[11];
    const float* Wout = (const float*)d_in[12];
    const float* bout = (const float*)d_in[13];
    const int* nid_ud = (const int*)d_in[14];
    const int* nid_us = (const int*)d_in[15];
    const int* nid_sp = (const int*)d_in[16];
    const int* e0s = (const int*)d_in[17];
    const int* e0d = (const int*)d_in[18];
    const int* e1s = (const int*)d_in[19];
    const int* e1d = (const int*)d_in[20];
    const int* e2s = (const int*)d_in[21];
    const int* e2d = (const int*)d_in[22];
    const int* e3s = (const int*)d_in[23];
    const int* e3d = (const int*)d_in[24];

    float *p_hud0, *p_hud1, *p_user0, *p_user1, *p_sup0, *p_sup1, *p_tuser, *p_agg;
    int *p_rowptr, *p_csrc;
    cudaGetSymbolAddress((void**)&p_hud0,  g_hud0);
    cudaGetSymbolAddress((void**)&p_hud1,  g_hud1);
    cudaGetSymbolAddress((void**)&p_user0, g_user0);
    cudaGetSymbolAddress((void**)&p_user1, g_user1);
    cudaGetSymbolAddress((void**)&p_sup0,  g_sup0);
    cudaGetSymbolAddress((void**)&p_sup1,  g_sup1);
    cudaGetSymbolAddress((void**)&p_tuser, g_tuser);
    cudaGetSymbolAddress((void**)&p_agg,   g_agg);
    cudaGetSymbolAddress((void**)&p_rowptr, g_rowptr);
    cudaGetSymbolAddress((void**)&p_csrc,   g_csrc);

    float* out    = (float*)d_out;
    float* o_pred = out;
    float* o_hud  = out + 1000000;
    float* o_user = out + 65000000;
    float* o_sup  = out + 65512000;

    cudaFuncSetAttribute(k_fused<1>, cudaFuncAttributeMaxDynamicSharedMemorySize, GB_SMEM_BYTES);
    cudaFuncSetAttribute(k_fused<2>, cudaFuncAttributeMaxDynamicSharedMemorySize, GB_SMEM_BYTES);

    const int T = 256;
    int gridZero  = (AGG_TOT/4 + T-1)/T;
    int gridUs32  = (N_USER*32 + T-1)/T;
    int gridSp32  = (N_SUP*32 + T-1)/T;
    int gridEB    = (E_BIG*32 + T-1)/T;
    int gridES    = (E_SMALL*32 + T-1)/T;
    int gridBig   = (N_UD + GB_TILE-1)/GB_TILE;
    int gridE1    = (E_BIG + T-1)/T;
    int gridN     = (N_UD + T-1)/T;

    // ---- init + CSR build for e1 (used by both fused GEMMs) ----
    k_zero_agg<<<gridZero, T>>>();
    k_zero_cnt<<<gridN, T>>>();
    k_hist<<<gridE1, T>>>(e1d);
    k_gather_rows<<<gridUs32, T>>>(emb_us, nid_us, p_user0, N_USER);
    k_gather_rows<<<gridSp32, T>>>(emb_sp, nid_sp, p_sup0, N_SUP);
    k_bsum<<<NBLK, 256>>>();
    k_scan_top<<<1, 512>>>();
    k_scan_write<<<NBLK, 1024>>>();
    k_fill<<<gridE1, T>>>(e1s, e1d);

    // ---- layer 1 UD: fused feat + GEMM + CSR scatter ----
    k_gemm_small<<<gridUs32, T>>>(p_user0, Wr1 + 1*HH, nullptr, p_tuser, N_USER, 0, 0);
    k_fused<1><<<gridBig, GB_THREADS, GB_SMEM_BYTES>>>(
        p_hud0, Wt1 + 1*HH, br1 + 1*H, p_tuser, p_rowptr, p_csrc, p_hud1,
        x_ud, nid_ud, emb_ud, W_feat, b_feat, p_hud0,
        nullptr, nullptr, nullptr, N_UD);

    // ---- layer 1 aggregations ----
    k_edge_add<false><<<gridEB, T>>>(p_hud0,  e0s, e0d, p_agg + L1_UB, E_BIG);
    k_edge_add<false><<<gridES, T>>>(p_sup0,  e3s, e3d, p_agg + L1_US, E_SMALL);
    k_edge_add<false><<<gridES, T>>>(p_user0, e2s, e2d, p_agg + L1_S,  E_SMALL);

    // ---- layer 1 user/sup outputs (post-relu stored) ----
    k_gemm_small<<<gridUs32, T>>>(p_agg + L1_UB, Wr1 + 0*HH, br1 + 0*H, p_user1, N_USER, 0, 0);
    k_gemm_small<<<gridUs32, T>>>(p_agg + L1_US, Wr1 + 3*HH, br1 + 3*H, p_user1, N_USER, 1, 0);
    k_gemm_small<<<gridUs32, T>>>(p_user0,       Wt1 + 0*HH, nullptr,   p_user1, N_USER, 1, 0);
    k_gemm_small<<<gridUs32, T>>>(p_user0,       Wt1 + 3*HH, nullptr,   p_user1, N_USER, 1, 1);
    k_gemm_small<<<gridSp32, T>>>(p_agg + L1_S,  Wr1 + 2*HH, br1 + 2*H, p_sup1,  N_SUP,  0, 0);
    k_gemm_small<<<gridSp32, T>>>(p_sup0,        Wt1 + 2*HH, nullptr,   p_sup1,  N_SUP,  1, 1);

    // ---- layer 2 aggregations ----
    k_edge_add<true ><<<gridEB, T>>>(p_hud1,  e0s, e0d, p_agg + L2_UB, E_BIG);
    k_edge_add<false><<<gridES, T>>>(p_sup1,  e3s, e3d, p_agg + L2_US, E_SMALL);
    k_edge_add<false><<<gridES, T>>>(p_user1, e2s, e2d, p_agg + L2_S,  E_SMALL);

    // ---- layer 2 user/sup outputs ----
    k_gemm_small<<<gridUs32, T>>>(p_agg + L2_UB, Wr2 + 0*HH, br2 + 0*H, o_user, N_USER, 0, 0);
    k_gemm_small<<<gridUs32, T>>>(p_agg + L2_US, Wr2 + 3*HH, br2 + 3*H, o_user, N_USER, 1, 0);
    k_gemm_small<<<gridUs32, T>>>(p_user1,       Wt2 + 0*HH, nullptr,   o_user, N_USER, 1, 0);
    k_gemm_small<<<gridUs32, T>>>(p_user1,       Wt2 + 3*HH, nullptr,   o_user, N_USER, 1, 0);
    k_gemm_small<<<gridSp32, T>>>(p_agg + L2_S,  Wr2 + 2*HH, br2 + 2*H, o_sup,  N_SUP,  0, 0);
    k_gemm_small<<<gridSp32, T>>>(p_sup1,        Wt2 + 2*HH, nullptr,   o_sup,  N_SUP,  1, 0);

    // ---- layer 2 UD: fused GEMM + CSR scatter + pred head ----
    k_gemm_small<<<gridUs32, T>>>(p_user1, Wr2 + 1*HH, nullptr, p_tuser, N_USER, 0, 0);
    k_fused<2><<<gridBig, GB_THREADS, GB_SMEM_BYTES>>>(
        p_hud1, Wt2 + 1*HH, br2 + 1*H, p_tuser, p_rowptr, p_csrc, o_hud,
        nullptr, nullptr, nullptr, nullptr, nullptr, nullptr,
        Wout, bout, o_pred, N_UD);

    (void)in_sizes; (void)n_in; (void)out_size;
}

// round 5
// speedup vs baseline: 1.1260x; 1.0445x over previous
#include <cuda_runtime.h>
#include <cuda_bf16.h>
#include <math.h>
#include <cstdint>

#define N_UD   500000
#define N_USER 4000
#define N_SUP  300
#define H      128
#define HH     (H*H)
#define E_BIG  500000
#define E_SMALL 4000
#define SZ_U   (N_USER*H)
#define SZ_S   (N_SUP*H)
#define NBLK   489   // ceil(N_UD/1024)
#define N_TILES 3907 // ceil(N_UD/128)

// ---------------- scratch (static __device__ -> no allocations) ----------------
__device__ __align__(16) float g_hud0[(size_t)N_UD*H];
__device__ __align__(16) float g_hud1[(size_t)N_UD*H];
__device__ __align__(16) float g_user0[SZ_U];
__device__ __align__(16) float g_user1[SZ_U];
__device__ __align__(16) float g_sup0[SZ_S];
__device__ __align__(16) float g_sup1[SZ_S];
__device__ __align__(16) float g_tuser[SZ_U];

// bf16-split, transposed weights for the two big GEMMs: B[n][k] = W[k][n]
__device__ __align__(16) __nv_bfloat16 g_Bhi[2*HH];
__device__ __align__(16) __nv_bfloat16 g_Blo[2*HH];

// CSR scratch for edge type 1 (user -> UD), keyed by dst (UD node)
__device__ int g_cnt[N_UD];
__device__ int g_rowptr[N_UD];
__device__ int g_pos[N_UD];
__device__ int g_csrc[E_BIG];
__device__ int g_bsum[NBLK];
__device__ int g_boff[NBLK];

#define AGG_TOT (2*(2*SZ_U+SZ_S))
__device__ __align__(16) float g_agg[AGG_TOT];
#define L1_UB 0
#define L1_US (SZ_U)
#define L1_S  (2*SZ_U)
#define L2_UB (2*SZ_U+SZ_S)
#define L2_US (L2_UB+SZ_U)
#define L2_S  (L2_UB+2*SZ_U)

// ---------------- helpers ----------------
__device__ __forceinline__ uint32_t smem_to_u32(const void* p) {
    uint32_t a;
    asm("{ .reg .u64 t; cvta.to.shared.u64 t, %1; cvt.u32.u64 %0, t; }" : "=r"(a) : "l"(p));
    return a;
}
__device__ __forceinline__ void red_add_v4(float* p, float4 v) {
    asm volatile("red.global.add.v4.f32 [%0], {%1,%2,%3,%4};"
                 :: "l"(p), "f"(v.x), "f"(v.y), "f"(v.z), "f"(v.w) : "memory");
}
__device__ __forceinline__ void ldsm_x4(uint32_t* r, uint32_t addr) {
    asm volatile("ldmatrix.sync.aligned.m8n8.x4.shared.b16 {%0,%1,%2,%3}, [%4];"
        : "=r"(r[0]), "=r"(r[1]), "=r"(r[2]), "=r"(r[3]) : "r"(addr));
}
__device__ __forceinline__ void mma_bf16(float* d, const uint32_t* a, const uint32_t* b) {
    asm volatile("mma.sync.aligned.m16n8k16.row.col.f32.bf16.bf16.f32 "
        "{%0,%1,%2,%3}, {%4,%5,%6,%7}, {%8,%9}, {%0,%1,%2,%3};"
        : "+f"(d[0]), "+f"(d[1]), "+f"(d[2]), "+f"(d[3])
        : "r"(a[0]), "r"(a[1]), "r"(a[2]), "r"(a[3]), "r"(b[0]), "r"(b[1]));
}

// ---------------- zero kernels ----------------
__global__ void k_zero_agg() {
    int g = blockIdx.x * blockDim.x + threadIdx.x;
    float4* p = (float4*)g_agg;
    if (g < AGG_TOT/4) p[g] = make_float4(0.f,0.f,0.f,0.f);
}
__global__ void k_zero_cnt() {
    int g = blockIdx.x * blockDim.x + threadIdx.x;
    if (g < N_UD) g_cnt[g] = 0;
}

// ---------------- CSR build (dst-keyed) ----------------
__global__ void k_hist(const int* __restrict__ ed) {
    int e = blockIdx.x * blockDim.x + threadIdx.x;
    if (e < E_BIG) atomicAdd(&g_cnt[ed[e]], 1);
}
__global__ void k_bsum() {
    __shared__ int s[256];
    int b = blockIdx.x, t = threadIdx.x;
    int sum = 0;
    for (int i = t; i < 1024; i += 256) {
        int idx = b*1024 + i;
        if (idx < N_UD) sum += g_cnt[idx];
    }
    s[t] = sum; __syncthreads();
    for (int o = 128; o > 0; o >>= 1) { if (t < o) s[t] += s[t+o]; __syncthreads(); }
    if (t == 0) g_bsum[b] = s[0];
}
__global__ void k_scan_top() {
    __shared__ int s[512];
    int t = threadIdx.x;
    int v = (t < NBLK) ? g_bsum[t] : 0;
    s[t] = v; __syncthreads();
    for (int o = 1; o < 512; o <<= 1) {
        int x = (t >= o) ? s[t-o] : 0;
        __syncthreads(); s[t] += x; __syncthreads();
    }
    if (t < NBLK) g_boff[t] = s[t] - v;
}
__global__ void k_scan_write() {
    __shared__ int s[1024];
    int b = blockIdx.x, t = threadIdx.x;
    int idx = b*1024 + t;
    int v = (idx < N_UD) ? g_cnt[idx] : 0;
    s[t] = v; __syncthreads();
    for (int o = 1; o < 1024; o <<= 1) {
        int x = (t >= o) ? s[t-o] : 0;
        __syncthreads(); s[t] += x; __syncthreads();
    }
    if (idx < N_UD) {
        int r = g_boff[b] + s[t] - v;
        g_rowptr[idx] = r;
        g_pos[idx] = r;
    }
}
__global__ void k_fill(const int* __restrict__ es, const int* __restrict__ ed) {
    int e = blockIdx.x * blockDim.x + threadIdx.x;
    if (e >= E_BIG) return;
    int p = atomicAdd(&g_pos[ed[e]], 1);
    g_csrc[p] = es[e];
}

// ---------------- weight prep: transpose + bf16 split ----------------
__global__ void k_prepW(const float* __restrict__ W0, const float* __restrict__ W1) {
    int i = blockIdx.x * blockDim.x + threadIdx.x;
    if (i >= 2*HH) return;
    int w = i >> 14;
    int r = i & (HH-1);
    int n = r >> 7, k = r & 127;
    const float* W = w ? W1 : W0;
    float v = W[k*H + n];
    __nv_bfloat16 hi = __float2bfloat16(v);
    float hf = __bfloat162float(hi);
    g_Bhi[i] = hi;
    g_Blo[i] = __float2bfloat16(v - hf);
}

// ---------------- gather embedding rows via nid ----------------
__global__ void k_gather_rows(const float* __restrict__ emb, const int* __restrict__ nid,
                              float* __restrict__ out, int M) {
    int g = blockIdx.x * blockDim.x + threadIdx.x;
    int row = g >> 5, lane = g & 31;
    if (row >= M) return;
    int r = nid[row];
    float4 v = *(const float4*)(emb + (size_t)r*H + lane*4);
    *(float4*)(out + (size_t)row*H + lane*4) = v;
}

// ---------------- edge scatter-add (small dst tables, L2-resident) ----------------
template<bool RELU>
__global__ void k_edge_add(const float* __restrict__ src_tab, const int* __restrict__ es,
                           const int* __restrict__ ed, float* __restrict__ dst_tab, int E) {
    int g = blockIdx.x * blockDim.x + threadIdx.x;
    int e = g >> 5;
    if (e >= E) return;
    int lane = g & 31;
    int s = es[e], d = ed[e];
    float4 v = *(const float4*)(src_tab + (size_t)s*H + lane*4);
    if (RELU) { v.x=fmaxf(v.x,0.f); v.y=fmaxf(v.y,0.f); v.z=fmaxf(v.z,0.f); v.w=fmaxf(v.w,0.f); }
    red_add_v4(dst_tab + (size_t)d*H + lane*4, v);
}

// ---------------- small GEMM ----------------
__global__ void k_gemm_small(const float* __restrict__ A, const float* __restrict__ W,
                             const float* __restrict__ bias, float* __restrict__ C,
                             int M, int accum, int relu) {
    int g = blockIdx.x * blockDim.x + threadIdx.x;
    int row = g >> 5;
    if (row >= M) return;
    int lane = g & 31;
    const float* a = A + (size_t)row*H;
    float4 acc = make_float4(0.f,0.f,0.f,0.f);
    #pragma unroll 8
    for (int k = 0; k < H; ++k) {
        float av = __ldg(a + k);
        float4 w = *(const float4*)(W + (size_t)k*H + lane*4);
        acc.x += av*w.x; acc.y += av*w.y; acc.z += av*w.z; acc.w += av*w.w;
    }
    if (bias) {
        float4 b = *(const float4*)(bias + lane*4);
        acc.x += b.x; acc.y += b.y; acc.z += b.z; acc.w += b.w;
    }
    float* cp = C + (size_t)row*H + lane*4;
    if (accum) {
        float4 old = *(float4*)cp;
        acc.x += old.x; acc.y += old.y; acc.z += old.z; acc.w += old.w;
    }
    if (relu) { acc.x=fmaxf(acc.x,0.f); acc.y=fmaxf(acc.y,0.f); acc.z=fmaxf(acc.z,0.f); acc.w=fmaxf(acc.w,0.f); }
    *(float4*)cp = acc;
}

// ================= fused big GEMM via mma.sync bf16 3-split =================
// MODE 1: A = feat(x_ud,Wf,bf,emb[nid]) (side-writes hud0); C = A@W + b + CSR(tuser)
// MODE 2: A = relu(Ain);  C = A@W + b + CSR(tuser); pred = log_softmax(C@Wout + bout)
// D = Ahi*Bhi + Ahi*Blo + Alo*Bhi, fp32 accumulators in registers.
#define PADB     272        // bytes per bf16 row (128+8 elements)
#define SM_W     0          // W_hi: 128*272 = 34816
#define SM_WLO   34816
#define SM_A     69632      // A_hi
#define SM_ALO   104448     // A_lo
#define SM_STAGE 69632      // overlays A after MMA: 128*132*4 = 67584
#define SM_BIAS  139264     // 128 f32
#define SM_EX    139776     // MODE1: Wf(640)+bf(128); MODE2: Wout(256)
#define TC_SMEM  143360
#define STG_STRIDE 132

template<int MODE>
__global__ __launch_bounds__(256, 1)
void k_fused_mma(const float* __restrict__ bias,
                 const float* __restrict__ tuser, const int* __restrict__ rowptr,
                 const int* __restrict__ csrc, float* __restrict__ C,
                 const float* __restrict__ Ain,
                 const float* __restrict__ xud, const int* __restrict__ nid,
                 const float* __restrict__ emb, const float* __restrict__ Wf,
                 const float* __restrict__ bf, float* __restrict__ hud0,
                 const float* __restrict__ Wout, const float* __restrict__ bout,
                 float* __restrict__ pred, const __nv_bfloat16* __restrict__ Bh,
                 const __nv_bfloat16* __restrict__ Bl, int M) {
    extern __shared__ char smem[];
    uint32_t smem_base = smem_to_u32(smem);
    float* sBias = (float*)(smem + SM_BIAS);
    float* sEx   = (float*)(smem + SM_EX);

    int tid  = threadIdx.x;
    int wid  = tid >> 5;
    int lane = tid & 31;
    long blockRow = (long)blockIdx.x * 128;

    // ---- stage weights + extras into smem ----
    if (tid < 128) sBias[tid] = bias[tid];
    if (MODE == 1) {
        for (int i = tid; i < 768; i += 256) sEx[i] = (i < 640) ? Wf[i] : bf[i-640];
    } else {
        if (tid < 256) sEx[tid] = Wout[tid];
    }
    for (int i = tid; i < 2048; i += 256) {       // 2048 uint4 = 16384 bf16
        uint4 vh = ((const uint4*)Bh)[i];
        uint4 vl = ((const uint4*)Bl)[i];
        int n  = i >> 4;
        int kq = i & 15;
        int dst = n*PADB + kq*16;
        *(uint4*)(smem + SM_W   + dst) = vh;
        *(uint4*)(smem + SM_WLO + dst) = vl;
    }
    __syncthreads();   // sEx visible for MODE1 feat compute

    // ---- prologue: build 128x128 A tile, bf16 hi/lo -> smem ----
    {
        int prow  = tid & 127;
        int khalf = tid >> 7;
        long rowReal = blockRow + prow;
        bool rok = rowReal < M;
        long rsrc = rok ? rowReal : (M-1);
        float x0=0,x1=0,x2=0,x3=0,x4=0; long nr = 0;
        if (MODE == 1) {
            nr = nid[rsrc];
            const float* xp = xud + rsrc*5;
            x0=xp[0]; x1=xp[1]; x2=xp[2]; x3=xp[3]; x4=xp[4];
        }
        #pragma unroll
        for (int j = 0; j < 16; ++j) {
            int k = khalf*64 + j*4;
            float4 o;
            if (MODE == 1) {
                float4 e  = *(const float4*)(emb + nr*H + k);
                float4 w0 = *(const float4*)(sEx + 0*H + k);
                float4 w1 = *(const float4*)(sEx + 1*H + k);
                float4 w2 = *(const float4*)(sEx + 2*H + k);
                float4 w3 = *(const float4*)(sEx + 3*H + k);
                float4 w4 = *(const float4*)(sEx + 4*H + k);
                float4 bb = *(const float4*)(sEx + 5*H + k);
                o.x = bb.x + e.x + x0*w0.x + x1*w1.x + x2*w2.x + x3*w3.x + x4*w4.x;
                o.y = bb.y + e.y + x0*w0.y + x1*w1.y + x2*w2.y + x3*w3.y + x4*w4.y;
                o.z = bb.z + e.z + x0*w0.z + x1*w1.z + x2*w2.z + x3*w3.z + x4*w4.z;
                o.w = bb.w + e.w + x0*w0.w + x1*w1.w + x2*w2.w + x3*w3.w + x4*w4.w;
                if (rok) *(float4*)(hud0 + rowReal*H + k) = o;
            } else {
                o = *(const float4*)(Ain + rsrc*H + k);
                o.x=fmaxf(o.x,0.f); o.y=fmaxf(o.y,0.f); o.z=fmaxf(o.z,0.f); o.w=fmaxf(o.w,0.f);
            }
            uint32_t h0, h1;
            asm("cvt.rn.bf16x2.f32 %0, %1, %2;" : "=r"(h0) : "f"(o.y), "f"(o.x));
            asm("cvt.rn.bf16x2.f32 %0, %1, %2;" : "=r"(h1) : "f"(o.w), "f"(o.z));
            float hx = __uint_as_float(h0 << 16);
            float hy = __uint_as_float(h0 & 0xffff0000u);
            float hz = __uint_as_float(h1 << 16);
            float hw = __uint_as_float(h1 & 0xffff0000u);
            uint32_t l0, l1;
            asm("cvt.rn.bf16x2.f32 %0, %1, %2;" : "=r"(l0) : "f"(o.y - hy), "f"(o.x - hx));
            asm("cvt.rn.bf16x2.f32 %0, %1, %2;" : "=r"(l1) : "f"(o.w - hw), "f"(o.z - hz));
            uint2 hh; hh.x = h0; hh.y = h1;
            uint2 ll; ll.x = l0; ll.y = l1;
            int off = prow*PADB + k*2;
            *(uint2*)(smem + SM_A   + off) = hh;
            *(uint2*)(smem + SM_ALO + off) = ll;
        }
    }
    __syncthreads();

    // ---- MMA mainloop: warp (wm, wn) owns 32 rows x 64 cols ----
    int wm = wid & 3, wn = wid >> 2;
    float acc[2][8][4];
    #pragma unroll
    for (int mt = 0; mt < 2; ++mt)
        #pragma unroll
        for (int nt = 0; nt < 8; ++nt)
            #pragma unroll
            for (int q = 0; q < 4; ++q) acc[mt][nt][q] = 0.f;

    #pragma unroll
    for (int kc = 0; kc < 8; ++kc) {
        uint32_t ah[2][4], al[2][4];
        #pragma unroll
        for (int mt = 0; mt < 2; ++mt) {
            int row  = wm*32 + mt*16 + (lane & 15);
            int koff = kc*16 + (lane >> 4)*8;
            uint32_t off = row*PADB + koff*2;
            ldsm_x4(ah[mt], smem_base + SM_A   + off);
            ldsm_x4(al[mt], smem_base + SM_ALO + off);
        }
        uint32_t bh[16], bl[16];
        #pragma unroll
        for (int g = 0; g < 4; ++g) {
            int n    = wn*64 + g*16 + (lane & 7) + (lane >> 4)*8;
            int koff = kc*16 + ((lane >> 3) & 1)*8;
            uint32_t off = n*PADB + koff*2;
            ldsm_x4(bh + g*4, smem_base + SM_W   + off);
            ldsm_x4(bl + g*4, smem_base + SM_WLO + off);
        }
        #pragma unroll
        for (int mt = 0; mt < 2; ++mt) {
            #pragma unroll
            for (int nt = 0; nt < 8; ++nt) {
                const uint32_t* bph = bh + (nt >> 1)*4 + (nt & 1)*2;
                const uint32_t* bpl = bl + (nt >> 1)*4 + (nt & 1)*2;
                mma_bf16(acc[mt][nt], ah[mt], bph);
                mma_bf16(acc[mt][nt], ah[mt], bpl);
                mma_bf16(acc[mt][nt], al[mt], bph);
            }
        }
    }

    // ---- stage accumulators to smem (overlays A) ----
    __syncthreads();
    float* stage = (float*)(smem + SM_STAGE);
    {
        int g = lane >> 2, t2 = (lane & 3)*2;
        #pragma unroll
        for (int mt = 0; mt < 2; ++mt) {
            #pragma unroll
            for (int nt = 0; nt < 8; ++nt) {
                int r0 = wm*32 + mt*16 + g;
                int c0 = wn*64 + nt*8 + t2;
                *(float2*)(stage + r0*STG_STRIDE + c0)     = make_float2(acc[mt][nt][0], acc[mt][nt][1]);
                *(float2*)(stage + (r0+8)*STG_STRIDE + c0) = make_float2(acc[mt][nt][2], acc[mt][nt][3]);
            }
        }
    }
    __syncthreads();

    // ---- epilogue: bias + CSR scatter + store (+pred) ----
    {
        int row  = tid >> 1;
        int half = tid & 1;
        long orow = blockRow + row;
        bool ok = orow < M;
        long rc = ok ? orow : (M-1);
        int beg = rowptr[rc];
        int end = (rc == N_UD-1) ? E_BIG : rowptr[rc+1];
        float v[64];
        const float* sp = stage + row*STG_STRIDE + half*64;
        #pragma unroll
        for (int j = 0; j < 16; ++j) {
            float4 t = *(const float4*)(sp + j*4);
            float4 b = *(const float4*)(sBias + half*64 + j*4);
            v[4*j+0]=t.x+b.x; v[4*j+1]=t.y+b.y; v[4*j+2]=t.z+b.z; v[4*j+3]=t.w+b.w;
        }
        for (int e = beg; e < end; ++e) {
            const float4* tp = (const float4*)(tuser + (size_t)csrc[e]*H + half*64);
            #pragma unroll
            for (int q = 0; q < 16; ++q) {
                float4 u = tp[q];
                v[4*q+0]+=u.x; v[4*q+1]+=u.y; v[4*q+2]+=u.z; v[4*q+3]+=u.w;
            }
        }
        if (ok) {
            float4* cp = (float4*)(C + orow*H + half*64);
            #pragma unroll
            for (int j = 0; j < 16; ++j)
                cp[j] = make_float4(v[4*j+0], v[4*j+1], v[4*j+2], v[4*j+3]);
        }
        if (MODE == 2) {
            float z0 = 0.f, z1 = 0.f;
            #pragma unroll
            for (int j = 0; j < 64; ++j) {
                int col = half*64 + j;
                z0 += v[j] * sEx[2*col];
                z1 += v[j] * sEx[2*col+1];
            }
            z0 += __shfl_xor_sync(0xffffffffu, z0, 1);
            z1 += __shfl_xor_sync(0xffffffffu, z1, 1);
            if (half == 0 && ok) {
                z0 += bout[0]; z1 += bout[1];
                float m = fmaxf(z0, z1);
                float l = m + logf(expf(z0 - m) + expf(z1 - m));
                *(float2*)(pred + orow*2) = make_float2(z0 - l, z1 - l);
            }
        }
    }
}

// ---------------- launch ----------------
extern "C" void kernel_launch(void* const* d_in, const int* in_sizes, int n_in,
                              void* d_out, int out_size) {
    const float* x_ud   = (const float*)d_in[0];
    const float* W_feat = (const float*)d_in[1];
    const float* b_feat = (const float*)d_in[2];
    const float* emb_ud = (const float*)d_in[3];
    const float* emb_us = (const float*)d_in[4];
    const float* emb_sp = (const float*)d_in[5];
    const float* Wr1 = (const float*)d_in[6];
    const float* br1 = (const float*)d_in[7];
    const float* Wt1 = (const float*)d_in[8];
    const float* Wr2 = (const float*)d_in[9];
    const float* br2 = (const float*)d_in[10];
    const float* Wt2 = (const float*)d_in[11];
    const float* Wout = (const float*)d_in[12];
    const float* bout = (const float*)d_in[13];
    const int* nid_ud = (const int*)d_in[14];
    const int* nid_us = (const int*)d_in[15];
    const int* nid_sp = (const int*)d_in[16];
    const int* e0s = (const int*)d_in[17];
    const int* e0d = (const int*)d_in[18];
    const int* e1s = (const int*)d_in[19];
    const int* e1d = (const int*)d_in[20];
    const int* e2s = (const int*)d_in[21];
    const int* e2d = (const int*)d_in[22];
    const int* e3s = (const int*)d_in[23];
    const int* e3d = (const int*)d_in[24];

    float *p_hud0, *p_hud1, *p_user0, *p_user1, *p_sup0, *p_sup1, *p_tuser, *p_agg;
    int *p_rowptr, *p_csrc;
    __nv_bfloat16 *p_bhi, *p_blo;
    cudaGetSymbolAddress((void**)&p_hud0,  g_hud0);
    cudaGetSymbolAddress((void**)&p_hud1,  g_hud1);
    cudaGetSymbolAddress((void**)&p_user0, g_user0);
    cudaGetSymbolAddress((void**)&p_user1, g_user1);
    cudaGetSymbolAddress((void**)&p_sup0,  g_sup0);
    cudaGetSymbolAddress((void**)&p_sup1,  g_sup1);
    cudaGetSymbolAddress((void**)&p_tuser, g_tuser);
    cudaGetSymbolAddress((void**)&p_agg,   g_agg);
    cudaGetSymbolAddress((void**)&p_rowptr, g_rowptr);
    cudaGetSymbolAddress((void**)&p_csrc,   g_csrc);
    cudaGetSymbolAddress((void**)&p_bhi,    g_Bhi);
    cudaGetSymbolAddress((void**)&p_blo,    g_Blo);

    float* out    = (float*)d_out;
    float* o_pred = out;
    float* o_hud  = out + 1000000;
    float* o_user = out + 65000000;
    float* o_sup  = out + 65512000;

    cudaFuncSetAttribute(k_fused_mma<1>, cudaFuncAttributeMaxDynamicSharedMemorySize, TC_SMEM);
    cudaFuncSetAttribute(k_fused_mma<2>, cudaFuncAttributeMaxDynamicSharedMemorySize, TC_SMEM);

    const int T = 256;
    int gridZero  = (AGG_TOT/4 + T-1)/T;
    int gridUs32  = (N_USER*32 + T-1)/T;
    int gridSp32  = (N_SUP*32 + T-1)/T;
    int gridEB    = (E_BIG*32 + T-1)/T;
    int gridES    = (E_SMALL*32 + T-1)/T;
    int gridE1    = (E_BIG + T-1)/T;
    int gridN     = (N_UD + T-1)/T;
    int gridPrep  = (2*HH + T-1)/T;

    // ---- init + CSR build + weight prep ----
    k_zero_agg<<<gridZero, T>>>();
    k_zero_cnt<<<gridN, T>>>();
    k_hist<<<gridE1, T>>>(e1d);
    k_prepW<<<gridPrep, T>>>(Wt1 + 1*HH, Wt2 + 1*HH);
    k_gather_rows<<<gridUs32, T>>>(emb_us, nid_us, p_user0, N_USER);
    k_gather_rows<<<gridSp32, T>>>(emb_sp, nid_sp, p_sup0, N_SUP);
    k_bsum<<<NBLK, 256>>>();
    k_scan_top<<<1, 512>>>();
    k_scan_write<<<NBLK, 1024>>>();
    k_fill<<<gridE1, T>>>(e1s, e1d);

    // ---- layer 1 UD: fused feat + MMA GEMM + CSR scatter ----
    k_gemm_small<<<gridUs32, T>>>(p_user0, Wr1 + 1*HH, nullptr, p_tuser, N_USER, 0, 0);
    k_fused_mma<1><<<N_TILES, 256, TC_SMEM>>>(
        br1 + 1*H, p_tuser, p_rowptr, p_csrc, p_hud1,
        nullptr, x_ud, nid_ud, emb_ud, W_feat, b_feat, p_hud0,
        nullptr, nullptr, nullptr, p_bhi, p_blo, N_UD);

    // ---- layer 1 aggregations ----
    k_edge_add<false><<<gridEB, T>>>(p_hud0,  e0s, e0d, p_agg + L1_UB, E_BIG);
    k_edge_add<false><<<gridES, T>>>(p_sup0,  e3s, e3d, p_agg + L1_US, E_SMALL);
    k_edge_add<false><<<gridES, T>>>(p_user0, e2s, e2d, p_agg + L1_S,  E_SMALL);

    // ---- layer 1 user/sup outputs (post-relu stored) ----
    k_gemm_small<<<gridUs32, T>>>(p_agg + L1_UB, Wr1 + 0*HH, br1 + 0*H, p_user1, N_USER, 0, 0);
    k_gemm_small<<<gridUs32, T>>>(p_agg + L1_US, Wr1 + 3*HH, br1 + 3*H, p_user1, N_USER, 1, 0);
    k_gemm_small<<<gridUs32, T>>>(p_user0,       Wt1 + 0*HH, nullptr,   p_user1, N_USER, 1, 0);
    k_gemm_small<<<gridUs32, T>>>(p_user0,       Wt1 + 3*HH, nullptr,   p_user1, N_USER, 1, 1);
    k_gemm_small<<<gridSp32, T>>>(p_agg + L1_S,  Wr1 + 2*HH, br1 + 2*H, p_sup1,  N_SUP,  0, 0);
    k_gemm_small<<<gridSp32, T>>>(p_sup0,        Wt1 + 2*HH, nullptr,   p_sup1,  N_SUP,  1, 1);

    // ---- layer 2 aggregations ----
    k_edge_add<true ><<<gridEB, T>>>(p_hud1,  e0s, e0d, p_agg + L2_UB, E_BIG);
    k_edge_add<false><<<gridES, T>>>(p_sup1,  e3s, e3d, p_agg + L2_US, E_SMALL);
    k_edge_add<false><<<gridES, T>>>(p_user1, e2s, e2d, p_agg + L2_S,  E_SMALL);

    // ---- layer 2 user/sup outputs ----
    k_gemm_small<<<gridUs32, T>>>(p_agg + L2_UB, Wr2 + 0*HH, br2 + 0*H, o_user, N_USER, 0, 0);
    k_gemm_small<<<gridUs32, T>>>(p_agg + L2_US, Wr2 + 3*HH, br2 + 3*H, o_user, N_USER, 1, 0);
    k_gemm_small<<<gridUs32, T>>>(p_user1,       Wt2 + 0*HH, nullptr,   o_user, N_USER, 1, 0);
    k_gemm_small<<<gridUs32, T>>>(p_user1,       Wt2 + 3*HH, nullptr,   o_user, N_USER, 1, 0);
    k_gemm_small<<<gridSp32, T>>>(p_agg + L2_S,  Wr2 + 2*HH, br2 + 2*H, o_sup,  N_SUP,  0, 0);
    k_gemm_small<<<gridSp32, T>>>(p_sup1,        Wt2 + 2*HH, nullptr,   o_sup,  N_SUP,  1, 0);

    // ---- layer 2 UD: fused relu + MMA GEMM + CSR scatter + pred head ----
    k_gemm_small<<<gridUs32, T>>>(p_user1, Wr2 + 1*HH, nullptr, p_tuser, N_USER, 0, 0);
    k_fused_mma<2><<<N_TILES, 256, TC_SMEM>>>(
        br2 + 1*H, p_tuser, p_rowptr, p_csrc, o_hud,
        p_hud1, nullptr, nullptr, nullptr, nullptr, nullptr, nullptr,
        Wout, bout, o_pred, p_bhi + HH, p_blo + HH, N_UD);

    (void)in_sizes; (void)n_in; (void)out_size;
}